// round 13
// baseline (speedup 1.0000x reference)
#include <cuda_runtime.h>
#include <cuda_bf16.h>
#include <math.h>
#include <stdint.h>

#define BB 4
#define CC 64
#define OO 64
#define DD 2
#define HH 128
#define WW 128
#define HW (HH*WW)

// Scratch: offset (B,18,D,H,W) and mask (B,9,D,H,W)
__device__ float g_off[BB*18*DD*HW];
__device__ float g_mask[BB*9*DD*HW];
// Prepacked bf16 deform-weight tiles per tap j: 64 rows(oc) x 128B, XOR-swizzled.
__device__ __nv_bfloat16 g_Bh[9][64*64];
__device__ __nv_bfloat16 g_Bl[9][64*64];
// Prepacked conv3d offset/mask weights: [od][dd*9+tap][32 oc x 64 ch], swizzled.
__device__ __nv_bfloat16 g_OWh[2][18][32*64];
__device__ __nv_bfloat16 g_OWl[2][18][32*64];

__device__ __forceinline__ uint32_t smem_to_u32(const void* p) {
    uint32_t a;
    asm("{ .reg .u64 t; cvta.to.shared.u64 t, %1; cvt.u32.u64 %0, t; }"
        : "=r"(a) : "l"(p));
    return a;
}

#define LDMATRIX_X4(r0, r1, r2, r3, addr) \
    asm volatile("ldmatrix.sync.aligned.m8n8.x4.shared.b16 {%0,%1,%2,%3}, [%4];" \
        : "=r"(r0), "=r"(r1), "=r"(r2), "=r"(r3) : "r"(addr))

#define MMA_BF16(c, a0, a1, a2, a3, b0, b1) \
    asm volatile("mma.sync.aligned.m16n8k16.row.col.f32.bf16.bf16.f32 " \
        "{%0,%1,%2,%3}, {%4,%5,%6,%7}, {%8,%9}, {%0,%1,%2,%3};" \
        : "+f"((c)[0]), "+f"((c)[1]), "+f"((c)[2]), "+f"((c)[3]) \
        : "r"(a0), "r"(a1), "r"(a2), "r"(a3), "r"(b0), "r"(b1))

#define STS_V4(addr, v0, v1, v2, v3) \
    asm volatile("st.shared.v4.u32 [%0], {%1,%2,%3,%4};" \
        :: "r"(addr), "r"(v0), "r"(v1), "r"(v2), "r"(v3) : "memory")

// Named split barriers, 512 participants. full[s]=1+s, empty[s]=3+s.
#define BAR_SYNC(id)   asm volatile("bar.sync %0, 512;"   :: "r"(id) : "memory")
#define BAR_ARRIVE(id) asm volatile("bar.arrive %0, 512;" :: "r"(id) : "memory")

// Split 8 fp32 -> 4 packed bf16x2 hi + 4 packed bf16x2 lo
__device__ __forceinline__ void cvt_split8(const float* v,
                                           uint32_t* hi, uint32_t* lo) {
#pragma unroll
    for (int k = 0; k < 4; k++) {
        __nv_bfloat16 h0 = __float2bfloat16(v[2*k]);
        __nv_bfloat16 h1 = __float2bfloat16(v[2*k+1]);
        hi[k] = (uint32_t)__bfloat16_as_ushort(h0)
              | ((uint32_t)__bfloat16_as_ushort(h1) << 16);
        float l0 = v[2*k]   - __bfloat162float(h0);
        float l1 = v[2*k+1] - __bfloat162float(h1);
        asm("cvt.rn.bf16x2.f32 %0, %1, %2;" : "=r"(lo[k]) : "f"(l1), "f"(l0));
    }
}

// Swizzled halfword index within a 64-halfword (128B) row: row r, channel c.
__device__ __forceinline__ int sw_idx(int r, int c) {
    return r*64 + (((c >> 3) ^ (r & 7)) << 3) + (c & 7);
}

// ---------------------------------------------------------------------------
// Kernel 0: pack all weights -> bf16 hi/lo swizzled tiles
// ---------------------------------------------------------------------------
__global__ void pack_w_kernel(const float* __restrict__ w0,
                              const float* __restrict__ ow,
                              const float* __restrict__ mw) {
    const int N1 = 9*4096;
    const int N2 = 2*18*2048;
    for (int i = threadIdx.x + blockIdx.x * blockDim.x; i < N1 + N2;
         i += blockDim.x * gridDim.x) {
        if (i < N1) {
            int j = i / 4096;
            int r = i - j*4096;
            int o = r >> 6;
            int c = r & 63;
            float v = w0[(o*CC + c)*9 + j];
            __nv_bfloat16 hb = __float2bfloat16(v);
            int s = sw_idx(o, c);
            g_Bh[j][s] = hb;
            g_Bl[j][s] = __float2bfloat16(v - __bfloat162float(hb));
        } else {
            int k = i - N1;
            int od = k / 36864;
            int r2 = k - od*36864;
            int jj = r2 >> 11;
            int q  = r2 & 2047;
            int o  = q >> 6;
            int c  = q & 63;
            int dd = jj / 9;
            int tap = jj - dd*9;
            int kd = dd + (od == 0 ? 1 : 0);
            float v = 0.f;
            if (o < 18)      v = ow[((o*CC + c)*3 + kd)*9 + tap];
            else if (o < 27) v = mw[(((o-18)*CC + c)*3 + kd)*9 + tap];
            __nv_bfloat16 hb = __float2bfloat16(v);
            int s = sw_idx(o, c);
            g_OWh[od][jj][s] = hb;
            g_OWl[od][jj][s] = __float2bfloat16(v - __bfloat162float(hb));
        }
    }
}

// ---------------------------------------------------------------------------
// Kernel 1: conv3d offset/mask — producer/consumer warp-specialized,
// 2 CTAs/SM. 512 threads: tid<256 producers; tid>=256 consumers.
// Double-buffered tiles. Grid (128, 2, 4).
// Buffer s: A_HI = s*40960, A_LO = +16384, B_HI = +32768, B_LO = +36864.
// ---------------------------------------------------------------------------
#define CV_BUF    40960
#define CV_TOTAL  81920

__global__ __launch_bounds__(512, 2)
void conv3d_mma_kernel(const float* __restrict__ x,
                       const float* __restrict__ ob,
                       const float* __restrict__ mb)
{
    extern __shared__ char smem[];
    const uint32_t smem_u = smem_to_u32(smem);
    const int tid   = threadIdx.x;
    const int wid   = tid >> 5;
    const int lane  = tid & 31;
    const int y   = blockIdx.x;
    const int od  = blockIdx.y;
    const int b   = blockIdx.z;

    if (tid < 256) {
        // ================= PRODUCERS =================
        const int pixel = tid & 127;
        const int half  = tid >> 7;
        const uint32_t arowb = (uint32_t)pixel * 128;
        const int swrow = pixel & 7;

#pragma unroll 1
        for (int jj = 0; jj < 18; jj++) {
            const int s = jj & 1;
            const uint32_t buf = smem_u + (uint32_t)s * CV_BUF;
            if (jj >= 2) BAR_SYNC(3 + s);

            // B tile: 256 units, one per producer thread
            {
                const uint4* sh = (const uint4*)(g_OWh[od][jj]);
                const uint4* sl = (const uint4*)(g_OWl[od][jj]);
                uint4 vh = sh[tid];
                uint4 vl = sl[tid];
                uint32_t dst = (uint32_t)tid * 16;
                STS_V4(buf + 32768 + dst, vh.x, vh.y, vh.z, vh.w);
                STS_V4(buf + 36864 + dst, vl.x, vl.y, vl.z, vl.w);
            }

            const int dd  = jj / 9;
            const int tap = jj - dd*9;
            const int yin = y - 1 + tap/3;
            const int xin = pixel - 1 + tap%3;
            const bool valid = ((unsigned)yin < (unsigned)HH) &&
                               ((unsigned)xin < (unsigned)WW);
            const float* xp0 = x + ((size_t)(b*CC)*DD + dd)*HW + yin*WW + xin;
#pragma unroll 2
            for (int g = 0; g < 4; g++) {
                float v[8];
#pragma unroll
                for (int k = 0; k < 8; k++) {
                    int c = half*32 + g*8 + k;
                    v[k] = valid ? xp0[(size_t)c*(DD*HW)] : 0.f;
                }
                uint32_t hi[4], lo[4];
                cvt_split8(v, hi, lo);
                uint32_t coff = (uint32_t)(((half*4 + g) ^ swrow) << 4);
                STS_V4(buf +     0 + arowb + coff, hi[0], hi[1], hi[2], hi[3]);
                STS_V4(buf + 16384 + arowb + coff, lo[0], lo[1], lo[2], lo[3]);
            }
            BAR_ARRIVE(1 + s);
        }
    } else {
        // ================= CONSUMERS =================
        const int cw = wid - 8;            // m-tile 0..7
        float acc[4][4];
#pragma unroll
        for (int nt = 0; nt < 4; nt++)
#pragma unroll
            for (int q = 0; q < 4; q++) acc[nt][q] = 0.f;

        const int agrp = lane >> 3;
        const int arow_off = (lane & 7) + ((agrp & 1) << 3);
        const int achunk   = (agrp >> 1);
        const int brow_off = (lane & 7) + ((agrp >> 1) << 3);
        const int bchunk   = (agrp & 1);

#pragma unroll 1
        for (int jj = 0; jj < 18; jj++) {
            const int s = jj & 1;
            const uint32_t buf = smem_u + (uint32_t)s * CV_BUF;
            BAR_SYNC(1 + s);

#pragma unroll
            for (int pass = 0; pass < 3; pass++) {
                const uint32_t Abase = buf + ((pass == 2) ? 16384 : 0);
                const uint32_t Bbase = buf + ((pass == 1) ? 36864 : 32768);
#pragma unroll
                for (int ks = 0; ks < 4; ks++) {
                    uint32_t a0, a1, a2, a3;
                    {
                        int rr = cw*16 + arow_off;
                        uint32_t addr = Abase + (uint32_t)rr*128
                            + (uint32_t)((((ks*2 + achunk) ^ (rr & 7)) << 4));
                        LDMATRIX_X4(a0, a1, a2, a3, addr);
                    }
#pragma unroll
                    for (int np = 0; np < 2; np++) {
                        uint32_t b0, b1, b2, b3;
                        int nn = np*16 + brow_off;
                        uint32_t addr = Bbase + (uint32_t)nn*128
                            + (uint32_t)((((ks*2 + bchunk) ^ (nn & 7)) << 4));
                        LDMATRIX_X4(b0, b1, b2, b3, addr);
                        MMA_BF16(acc[np*2],   a0, a1, a2, a3, b0, b1);
                        MMA_BF16(acc[np*2+1], a0, a1, a2, a3, b2, b3);
                    }
                }
            }
            BAR_ARRIVE(3 + s);
        }

        // epilogue: bias + sigmoid, write g_off / g_mask
        int prow = cw*16 + (lane >> 2);
#pragma unroll
        for (int nt = 0; nt < 4; nt++) {
            int oc0 = nt*8 + 2*(lane & 3);
#pragma unroll
            for (int q = 0; q < 4; q++) {
                int oc = oc0 + (q & 1);
                int p  = prow + ((q >> 1) << 3);
                float v = acc[nt][q];
                int pixo = y*WW + p;
                if (oc < 18) {
                    g_off[((b*18 + oc)*DD + od)*HW + pixo] = v + ob[oc];
                } else if (oc < 27) {
                    float t = v + mb[oc - 18];
                    g_mask[((b*9 + oc - 18)*DD + od)*HW + pixo] =
                        2.f / (1.f + expf(-t));
                }
            }
        }
    }
}

// ---------------------------------------------------------------------------
// Kernel 2: deformable conv — producer/consumer warp-specialized, 2 CTAs/SM.
// 512 threads: tid<256 producers; tid>=256 consumers. Double-buffered.
// Grid (128, 2, 4). Buffer s: A_HI = s*49152, A_LO = +16384, B_HI = +32768,
// B_LO = +40960.
// ---------------------------------------------------------------------------
#define SM_BUF    49152
#define SM_TOTAL  98304

__global__ __launch_bounds__(512, 2)
void deform_mma_kernel(const float* __restrict__ x, float* __restrict__ out)
{
    extern __shared__ char smem[];
    const uint32_t smem_u = smem_to_u32(smem);
    const int tid   = threadIdx.x;
    const int wid   = tid >> 5;
    const int lane  = tid & 31;
    const int y   = blockIdx.x;
    const int d   = blockIdx.y;
    const int b   = blockIdx.z;

    if (tid < 256) {
        // ================= PRODUCERS =================
        const int pixel = tid & 127;
        const int half  = tid >> 7;
        const int pix   = y*WW + pixel;
        const uint32_t arowb = (uint32_t)pixel * 128;
        const int swrow = pixel & 7;
        const float* xbase = x + ((size_t)b*CC*DD + d) * HW;

#pragma unroll 1
        for (int j = 0; j < 9; j++) {
            const int s = j & 1;
            const uint32_t buf = smem_u + (uint32_t)s * SM_BUF;
            if (j >= 2) BAR_SYNC(3 + s);

            // B tile: 512 units, two per producer thread
            {
                const uint4* sh = (const uint4*)(g_Bh[j]);
                const uint4* sl = (const uint4*)(g_Bl[j]);
#pragma unroll
                for (int it = 0; it < 2; it++) {
                    int u = tid + 256*it;
                    uint4 vh = sh[u];
                    uint4 vl = sl[u];
                    uint32_t dst = (uint32_t)u * 16;
                    STS_V4(buf + 32768 + dst, vh.x, vh.y, vh.z, vh.w);
                    STS_V4(buf + 40960 + dst, vl.x, vl.y, vl.z, vl.w);
                }
            }

            // sampling setup
            float dy = g_off[((b*18 + 2*j    )*DD + d)*HW + pix];
            float dx = g_off[((b*18 + 2*j + 1)*DD + d)*HW + pix];
            float m  = g_mask[((b*9 + j)*DD + d)*HW + pix];
            float py = (float)(y     - 1 + j/3) + dy;
            float px = (float)(pixel - 1 + j%3) + dx;
            float fy = floorf(py), fx = floorf(px);
            float ly = py - fy,    lx = px - fx;
            float hy = 1.f - ly,   hx = 1.f - lx;
            int iy0 = (int)fy, ix0 = (int)fx;
            int iy1 = iy0 + 1, ix1 = ix0 + 1;
            bool vy0 = ((unsigned)iy0 < (unsigned)HH);
            bool vy1 = ((unsigned)iy1 < (unsigned)HH);
            bool vx0 = ((unsigned)ix0 < (unsigned)WW);
            bool vx1 = ((unsigned)ix1 < (unsigned)WW);
            float a00 = (vy0 && vx0) ? hy*hx*m : 0.f;
            float a01 = (vy0 && vx1) ? hy*lx*m : 0.f;
            float a10 = (vy1 && vx0) ? ly*hx*m : 0.f;
            float a11 = (vy1 && vx1) ? ly*lx*m : 0.f;
            int yr0 = min(max(iy0, 0), HH-1)*WW;
            int yr1 = min(max(iy1, 0), HH-1)*WW;
            int xr0 = min(max(ix0, 0), WW-1);
            int xr1 = min(max(ix1, 0), WW-1);
            int o00 = yr0 + xr0, o01 = yr0 + xr1;
            int o10 = yr1 + xr0, o11 = yr1 + xr1;

#pragma unroll 2
            for (int g = 0; g < 4; g++) {
                float v[8];
#pragma unroll
                for (int k = 0; k < 8; k++) {
                    const float* xp = xbase + (size_t)(half*32 + g*8 + k)*(DD*HW);
                    v[k] = a00*xp[o00] + a01*xp[o01] + a10*xp[o10] + a11*xp[o11];
                }
                uint32_t hi[4], lo[4];
                cvt_split8(v, hi, lo);
                uint32_t coff = (uint32_t)(((half*4 + g) ^ swrow) << 4);
                STS_V4(buf +     0 + arowb + coff, hi[0], hi[1], hi[2], hi[3]);
                STS_V4(buf + 16384 + arowb + coff, lo[0], lo[1], lo[2], lo[3]);
            }
            BAR_ARRIVE(1 + s);
        }
    } else {
        // ================= CONSUMERS =================
        const int cw = wid - 8;            // m-tile 0..7
        float acc[8][4];
#pragma unroll
        for (int nt = 0; nt < 8; nt++)
#pragma unroll
            for (int q = 0; q < 4; q++) acc[nt][q] = 0.f;

        const int agrp = lane >> 3;
        const int arow_off = (lane & 7) + ((agrp & 1) << 3);
        const int achunk   = (agrp >> 1);
        const int brow_off = (lane & 7) + ((agrp >> 1) << 3);
        const int bchunk   = (agrp & 1);

#pragma unroll 1
        for (int j = 0; j < 9; j++) {
            const int s = j & 1;
            const uint32_t buf = smem_u + (uint32_t)s * SM_BUF;
            BAR_SYNC(1 + s);

#pragma unroll
            for (int pass = 0; pass < 3; pass++) {
                const uint32_t Abase = buf + ((pass == 2) ? 16384 : 0);
                const uint32_t Bbase = buf + ((pass == 1) ? 40960 : 32768);
#pragma unroll
                for (int ks = 0; ks < 4; ks++) {
                    uint32_t a0, a1, a2, a3;
                    {
                        int rr = cw*16 + arow_off;
                        uint32_t addr = Abase + (uint32_t)rr*128
                            + (uint32_t)((((ks*2 + achunk) ^ (rr & 7)) << 4));
                        LDMATRIX_X4(a0, a1, a2, a3, addr);
                    }
#pragma unroll
                    for (int np = 0; np < 4; np++) {
                        uint32_t b0, b1, b2, b3;
                        int nn = np*16 + brow_off;
                        uint32_t addr = Bbase + (uint32_t)nn*128
                            + (uint32_t)((((ks*2 + bchunk) ^ (nn & 7)) << 4));
                        LDMATRIX_X4(b0, b1, b2, b3, addr);
                        MMA_BF16(acc[np*2],   a0, a1, a2, a3, b0, b1);
                        MMA_BF16(acc[np*2+1], a0, a1, a2, a3, b2, b3);
                    }
                }
            }
            BAR_ARRIVE(3 + s);
        }

        // epilogue
        int xr = cw*16 + (lane >> 2);
        float* op0 = out + ((size_t)b*OO*DD + d)*HW + y*WW + xr;
#pragma unroll
        for (int nt = 0; nt < 8; nt++) {
            int oc = nt*8 + 2*(lane & 3);
            op0[(size_t)(oc  )*DD*HW    ] = acc[nt][0];
            op0[(size_t)(oc+1)*DD*HW    ] = acc[nt][1];
            op0[(size_t)(oc  )*DD*HW + 8] = acc[nt][2];
            op0[(size_t)(oc+1)*DD*HW + 8] = acc[nt][3];
        }
    }
}

// ---------------------------------------------------------------------------
// Launch
// ---------------------------------------------------------------------------
extern "C" void kernel_launch(void* const* d_in, const int* in_sizes, int n_in,
                              void* d_out, int out_size)
{
    const float* x  = (const float*)d_in[0];
    const float* ow = (const float*)d_in[1];
    const float* ob = (const float*)d_in[2];
    const float* mw = (const float*)d_in[3];
    const float* mb = (const float*)d_in[4];
    const float* w0 = (const float*)d_in[5];
    float* out = (float*)d_out;

    cudaFuncSetAttribute(deform_mma_kernel,
                         cudaFuncAttributeMaxDynamicSharedMemorySize, SM_TOTAL);
    cudaFuncSetAttribute(conv3d_mma_kernel,
                         cudaFuncAttributeMaxDynamicSharedMemorySize, CV_TOTAL);

    dim3 grid(HH, DD, BB);
    pack_w_kernel<<<120, 256>>>(w0, ow, mw);
    conv3d_mma_kernel<<<grid, 512, CV_TOTAL>>>(x, ob, mb);
    deform_mma_kernel<<<grid, 512, SM_TOTAL>>>(x, out);
}

// round 16
// speedup vs baseline: 1.6026x; 1.6026x over previous
#include <cuda_runtime.h>
#include <math.h>
#include <stdint.h>

#define BB 4
#define CC 64
#define OO 64
#define DD 2
#define HH 128
#define WW 128
#define HW (HH*WW)

// Scratch: offset (B,18,D,H,W) and mask (B,9,D,H,W)
__device__ float g_off[BB*18*DD*HW];
__device__ float g_mask[BB*9*DD*HW];
// Prepacked tf32 deform-weight tiles per tap j: 64 rows(oc) x 256B, swizzled.
__device__ float g_Bt[9][64*64];
// Prepacked conv3d offset/mask weights: [od][dd*9+tap][32 oc x 64 ch], swizzled.
__device__ float g_OWt[2][18][32*64];

__device__ __forceinline__ uint32_t smem_to_u32(const void* p) {
    uint32_t a;
    asm("{ .reg .u64 t; cvta.to.shared.u64 t, %1; cvt.u32.u64 %0, t; }"
        : "=r"(a) : "l"(p));
    return a;
}

// cvt to tf32 has a b32 destination in PTX.
__device__ __forceinline__ uint32_t to_tf32_bits(float v) {
    uint32_t r;
    asm("cvt.rna.tf32.f32 %0, %1;" : "=r"(r) : "f"(v));
    return r;
}

#define LDMATRIX_X4(r0, r1, r2, r3, addr) \
    asm volatile("ldmatrix.sync.aligned.m8n8.x4.shared.b16 {%0,%1,%2,%3}, [%4];" \
        : "=r"(r0), "=r"(r1), "=r"(r2), "=r"(r3) : "r"(addr))

#define MMA_TF32(c, a0, a1, a2, a3, b0, b1) \
    asm volatile("mma.sync.aligned.m16n8k8.row.col.f32.tf32.tf32.f32 " \
        "{%0,%1,%2,%3}, {%4,%5,%6,%7}, {%8,%9}, {%0,%1,%2,%3};" \
        : "+f"((c)[0]), "+f"((c)[1]), "+f"((c)[2]), "+f"((c)[3]) \
        : "r"(a0), "r"(a1), "r"(a2), "r"(a3), "r"(b0), "r"(b1))

#define STS_V4(addr, v0, v1, v2, v3) \
    asm volatile("st.shared.v4.u32 [%0], {%1,%2,%3,%4};" \
        :: "r"(addr), "r"(v0), "r"(v1), "r"(v2), "r"(v3) : "memory")

// Swizzled float index within a 64-float (256B) row: row r, channel c.
// 16 chunks of 16B; phys chunk = (c>>2) ^ (r & 15).
__device__ __forceinline__ int sw_idx32(int r, int c) {
    return r*64 + ((((c >> 2) ^ (r & 15))) << 2) + (c & 3);
}

// ---------------------------------------------------------------------------
// Kernel 0: pack all weights -> tf32 swizzled tiles
// ---------------------------------------------------------------------------
__global__ void pack_w_kernel(const float* __restrict__ w0,
                              const float* __restrict__ ow,
                              const float* __restrict__ mw) {
    const int N1 = 9*4096;
    const int N2 = 2*18*2048;
    for (int i = threadIdx.x + blockIdx.x * blockDim.x; i < N1 + N2;
         i += blockDim.x * gridDim.x) {
        if (i < N1) {
            int j = i / 4096;
            int r = i - j*4096;
            int o = r >> 6;
            int c = r & 63;
            float v = w0[(o*CC + c)*9 + j];
            g_Bt[j][sw_idx32(o, c)] = __uint_as_float(to_tf32_bits(v));
        } else {
            int k = i - N1;
            int od = k / 36864;
            int r2 = k - od*36864;
            int jj = r2 >> 11;
            int q  = r2 & 2047;
            int o  = q >> 6;
            int c  = q & 63;
            int dd = jj / 9;
            int tap = jj - dd*9;
            int kd = dd + (od == 0 ? 1 : 0);
            float v = 0.f;
            if (o < 18)      v = ow[((o*CC + c)*3 + kd)*9 + tap];
            else if (o < 27) v = mw[(((o-18)*CC + c)*3 + kd)*9 + tap];
            g_OWt[od][jj][sw_idx32(o, c)] = __uint_as_float(to_tf32_bits(v));
        }
    }
}

// ---------------------------------------------------------------------------
// Kernel 1: conv3d offset/mask via single-pass tf32 mma.
// 256 threads, 2 CTAs/SM. (pixel = tid&127, half = tid>>7). Grid (128, 2, 4).
// A: 128 rows x 256B (tf32, swizzled). B: 32 rows x 256B.
// 8 warps, each one 16-row m-tile x 4 n8-tiles.
// ---------------------------------------------------------------------------
#define CV_A      0
#define CV_B      32768
#define CV_TOTAL  40960

__global__ __launch_bounds__(256, 2)
void conv3d_mma_kernel(const float* __restrict__ x,
                       const float* __restrict__ ob,
                       const float* __restrict__ mb)
{
    extern __shared__ char smem[];
    const uint32_t smem_u = smem_to_u32(smem);
    const int tid   = threadIdx.x;
    const int wid   = tid >> 5;
    const int lane  = tid & 31;
    const int pixel = tid & 127;
    const int half  = tid >> 7;
    const int y   = blockIdx.x;
    const int od  = blockIdx.y;
    const int b   = blockIdx.z;

    float acc[4][4];
#pragma unroll
    for (int nt = 0; nt < 4; nt++)
#pragma unroll
        for (int q = 0; q < 4; q++) acc[nt][q] = 0.f;

    // ldmatrix lane address components
    const int mi   = lane >> 3;            // matrix index 0..3
    const int lrow = lane & 7;
    const int arow_off = lrow + ((mi & 1) << 3);
    const int achq     = (mi >> 1);
    const int bnt_off = (mi >> 1);
    const int bquad   = (mi & 1);

#pragma unroll 1
    for (int jj = 0; jj < 18; jj++) {
        const int dd  = jj / 9;
        const int tap = jj - dd*9;

        // ---- B tile copy: 8KB = 512 uint4, 2 per thread ----
        {
            const uint4* sb = (const uint4*)(g_OWt[od][jj]);
#pragma unroll
            for (int it = 0; it < 2; it++) {
                int u = tid + 256*it;
                uint4 v = sb[u];
                STS_V4(smem_u + CV_B + (uint32_t)u*16, v.x, v.y, v.z, v.w);
            }
        }

        // ---- A tile: 32 channels (this half), shifted coalesced reads ----
        const int yin = y - 1 + tap/3;
        const int xin = pixel - 1 + tap%3;
        const bool valid = ((unsigned)yin < (unsigned)HH) &&
                           ((unsigned)xin < (unsigned)WW);
        const float* xp0 = x + ((size_t)(b*CC)*DD + dd)*HW + yin*WW + xin;
        const uint32_t arowb = (uint32_t)pixel * 256;
        const int r15 = pixel & 15;
#pragma unroll 2
        for (int g = 0; g < 4; g++) {        // 8 channels per g
            uint32_t t[8];
#pragma unroll
            for (int k = 0; k < 8; k++) {
                int c = half*32 + g*8 + k;
                float v = valid ? xp0[(size_t)c*(DD*HW)] : 0.f;
                t[k] = to_tf32_bits(v);
            }
            int lc0 = half*8 + g*2;
            STS_V4(smem_u + CV_A + arowb + (uint32_t)(((lc0    ) ^ r15) << 4),
                   t[0], t[1], t[2], t[3]);
            STS_V4(smem_u + CV_A + arowb + (uint32_t)(((lc0 + 1) ^ r15) << 4),
                   t[4], t[5], t[6], t[7]);
        }

        __syncthreads();

        // ---- MMA: warp wid = m-tile, 8 k-steps of 8 channels ----
#pragma unroll
        for (int ks = 0; ks < 8; ks++) {
            uint32_t a0, a1, a2, a3;
            {
                int rr = wid*16 + arow_off;
                int lc = ks*2 + achq;
                uint32_t addr = smem_u + CV_A + (uint32_t)rr*256
                              + (uint32_t)((lc ^ (rr & 15)) << 4);
                LDMATRIX_X4(a0, a1, a2, a3, addr);
            }
#pragma unroll
            for (int nb = 0; nb < 2; nb++) {   // 2 n-tiles per x4
                uint32_t b0, b1, b2, b3;
                int nn = (nb*2 + bnt_off)*8 + lrow;
                int lc = ks*2 + bquad;
                uint32_t addr = smem_u + CV_B + (uint32_t)nn*256
                              + (uint32_t)((lc ^ (nn & 15)) << 4);
                LDMATRIX_X4(b0, b1, b2, b3, addr);
                MMA_TF32(acc[nb*2],   a0, a1, a2, a3, b0, b1);
                MMA_TF32(acc[nb*2+1], a0, a1, a2, a3, b2, b3);
            }
        }
        __syncthreads();
    }

    // ---- epilogue: bias + sigmoid, write g_off / g_mask ----
    {
        int prow = wid*16 + (lane >> 2);
#pragma unroll
        for (int nt = 0; nt < 4; nt++) {
            int oc0 = nt*8 + 2*(lane & 3);
#pragma unroll
            for (int q = 0; q < 4; q++) {
                int oc = oc0 + (q & 1);
                int p  = prow + ((q >> 1) << 3);
                float v = acc[nt][q];
                int pixo = y*WW + p;
                if (oc < 18) {
                    g_off[((b*18 + oc)*DD + od)*HW + pixo] = v + ob[oc];
                } else if (oc < 27) {
                    float t = v + mb[oc - 18];
                    g_mask[((b*9 + oc - 18)*DD + od)*HW + pixo] =
                        2.f / (1.f + expf(-t));
                }
            }
        }
    }
}

// ---------------------------------------------------------------------------
// Kernel 2: deformable conv via single-pass tf32 mma.
// 256 threads, 2 CTAs/SM. (pixel, half). Grid (128, 2, 4).
// A: 128 x 256B tf32 swizzled; B: 64 x 256B. 8 warps, m-tile x 8 n8-tiles.
// ---------------------------------------------------------------------------
#define SM_A      0
#define SM_B      32768
#define SM_TOTAL  49152

__global__ __launch_bounds__(256, 2)
void deform_mma_kernel(const float* __restrict__ x, float* __restrict__ out)
{
    extern __shared__ char smem[];
    const uint32_t smem_u = smem_to_u32(smem);
    const int tid   = threadIdx.x;
    const int wid   = tid >> 5;
    const int lane  = tid & 31;
    const int pixel = tid & 127;
    const int half  = tid >> 7;
    const int y   = blockIdx.x;
    const int d   = blockIdx.y;
    const int b   = blockIdx.z;
    const int pix = y*WW + pixel;

    float acc[8][4];
#pragma unroll
    for (int nt = 0; nt < 8; nt++)
#pragma unroll
        for (int q = 0; q < 4; q++) acc[nt][q] = 0.f;

    const float* xbase = x + ((size_t)b*CC*DD + d) * HW;

    const int mi   = lane >> 3;
    const int lrow = lane & 7;
    const int arow_off = lrow + ((mi & 1) << 3);
    const int achq     = (mi >> 1);
    const int bnt_off  = (mi >> 1);
    const int bquad    = (mi & 1);

#pragma unroll 1
    for (int j = 0; j < 9; j++) {
        // ---- B tile copy: 16KB = 1024 uint4, 4 per thread ----
        {
            const uint4* sb = (const uint4*)(g_Bt[j]);
#pragma unroll
            for (int it = 0; it < 4; it++) {
                int u = tid + 256*it;
                uint4 v = sb[u];
                STS_V4(smem_u + SM_B + (uint32_t)u*16, v.x, v.y, v.z, v.w);
            }
        }

        // ---- per-pixel sampling setup ----
        float dy = g_off[((b*18 + 2*j    )*DD + d)*HW + pix];
        float dx = g_off[((b*18 + 2*j + 1)*DD + d)*HW + pix];
        float m  = g_mask[((b*9 + j)*DD + d)*HW + pix];
        float py = (float)(y     - 1 + j/3) + dy;
        float px = (float)(pixel - 1 + j%3) + dx;
        float fy = floorf(py), fx = floorf(px);
        float ly = py - fy,    lx = px - fx;
        float hy = 1.f - ly,   hx = 1.f - lx;
        int iy0 = (int)fy, ix0 = (int)fx;
        int iy1 = iy0 + 1, ix1 = ix0 + 1;
        bool vy0 = ((unsigned)iy0 < (unsigned)HH);
        bool vy1 = ((unsigned)iy1 < (unsigned)HH);
        bool vx0 = ((unsigned)ix0 < (unsigned)WW);
        bool vx1 = ((unsigned)ix1 < (unsigned)WW);
        float a00 = (vy0 && vx0) ? hy*hx*m : 0.f;
        float a01 = (vy0 && vx1) ? hy*lx*m : 0.f;
        float a10 = (vy1 && vx0) ? ly*hx*m : 0.f;
        float a11 = (vy1 && vx1) ? ly*lx*m : 0.f;
        int yr0 = min(max(iy0, 0), HH-1)*WW;
        int yr1 = min(max(iy1, 0), HH-1)*WW;
        int xr0 = min(max(ix0, 0), WW-1);
        int xr1 = min(max(ix1, 0), WW-1);
        int o00 = yr0 + xr0, o01 = yr0 + xr1;
        int o10 = yr1 + xr0, o11 = yr1 + xr1;

        // ---- A tile: 32 channels (this half), coalesced gathers ----
        const uint32_t arowb = (uint32_t)pixel * 256;
        const int r15 = pixel & 15;
#pragma unroll 2
        for (int g = 0; g < 4; g++) {        // 8 channels per g
            uint32_t t[8];
#pragma unroll
            for (int k = 0; k < 8; k++) {
                const float* xp = xbase + (size_t)(half*32 + g*8 + k)*(DD*HW);
                float v = a00*xp[o00] + a01*xp[o01] + a10*xp[o10] + a11*xp[o11];
                t[k] = to_tf32_bits(v);
            }
            int lc0 = half*8 + g*2;
            STS_V4(smem_u + SM_A + arowb + (uint32_t)(((lc0    ) ^ r15) << 4),
                   t[0], t[1], t[2], t[3]);
            STS_V4(smem_u + SM_A + arowb + (uint32_t)(((lc0 + 1) ^ r15) << 4),
                   t[4], t[5], t[6], t[7]);
        }

        __syncthreads();

        // ---- MMA: warp wid = m-tile, 8 k-steps ----
#pragma unroll
        for (int ks = 0; ks < 8; ks++) {
            uint32_t a0, a1, a2, a3;
            {
                int rr = wid*16 + arow_off;
                int lc = ks*2 + achq;
                uint32_t addr = smem_u + SM_A + (uint32_t)rr*256
                              + (uint32_t)((lc ^ (rr & 15)) << 4);
                LDMATRIX_X4(a0, a1, a2, a3, addr);
            }
#pragma unroll
            for (int nb = 0; nb < 4; nb++) {   // 2 n-tiles per x4, 8 total
                uint32_t b0, b1, b2, b3;
                int nn = (nb*2 + bnt_off)*8 + lrow;
                int lc = ks*2 + bquad;
                uint32_t addr = smem_u + SM_B + (uint32_t)nn*256
                              + (uint32_t)((lc ^ (nn & 15)) << 4);
                LDMATRIX_X4(b0, b1, b2, b3, addr);
                MMA_TF32(acc[nb*2],   a0, a1, a2, a3, b0, b1);
                MMA_TF32(acc[nb*2+1], a0, a1, a2, a3, b2, b3);
            }
        }
        __syncthreads();
    }

    // ---- epilogue ----
    {
        int xr = wid*16 + (lane >> 2);
        float* op0 = out + ((size_t)b*OO*DD + d)*HW + y*WW + xr;
#pragma unroll
        for (int nt = 0; nt < 8; nt++) {
            int oc = nt*8 + 2*(lane & 3);
            op0[(size_t)(oc  )*DD*HW    ] = acc[nt][0];
            op0[(size_t)(oc+1)*DD*HW    ] = acc[nt][1];
            op0[(size_t)(oc  )*DD*HW + 8] = acc[nt][2];
            op0[(size_t)(oc+1)*DD*HW + 8] = acc[nt][3];
        }
    }
}

// ---------------------------------------------------------------------------
// Launch
// ---------------------------------------------------------------------------
extern "C" void kernel_launch(void* const* d_in, const int* in_sizes, int n_in,
                              void* d_out, int out_size)
{
    const float* x  = (const float*)d_in[0];
    const float* ow = (const float*)d_in[1];
    const float* ob = (const float*)d_in[2];
    const float* mw = (const float*)d_in[3];
    const float* mb = (const float*)d_in[4];
    const float* w0 = (const float*)d_in[5];
    float* out = (float*)d_out;

    cudaFuncSetAttribute(deform_mma_kernel,
                         cudaFuncAttributeMaxDynamicSharedMemorySize, SM_TOTAL);
    cudaFuncSetAttribute(conv3d_mma_kernel,
                         cudaFuncAttributeMaxDynamicSharedMemorySize, CV_TOTAL);

    dim3 grid(HH, DD, BB);
    pack_w_kernel<<<120, 256>>>(w0, ow, mw);
    conv3d_mma_kernel<<<grid, 256, CV_TOTAL>>>(x, ob, mb);
    deform_mma_kernel<<<grid, 256, SM_TOTAL>>>(x, out);
}